// round 1
// baseline (speedup 1.0000x reference)
#include <cuda_runtime.h>
#include <math.h>
#include <stdint.h>

#define KCODES   8192
#define DIM      256
#define NTOK     8192       // B*H*W = 8*32*32
#define HWSZ     1024       // H*W
#define ZQ_ELEMS 2097152    // B*D*H*W
#define OUT_FULL (ZQ_ELEMS + 2 + NTOK)
#define CAP      1024

static __device__ float    g_flat[NTOK * DIM];   // z_e transposed to [N, D]
static __device__ float    g_w2[KCODES];         // |w_k|^2
static __device__ unsigned g_wmax2_bits;         // max_k |w_k|^2 (bits, >=0 so uint-ordered)
static __device__ int      g_idx[NTOK];
static __device__ int      g_hist[KCODES];
static __device__ double   g_loss;

// ---------------- zero scratch (must be re-zeroed every graph replay) --------
__global__ void k_zero() {
    int i = blockIdx.x * blockDim.x + threadIdx.x;
    if (i < KCODES) g_hist[i] = 0;
    if (i == 0) { g_loss = 0.0; g_wmax2_bits = 0u; }
}

// ---------------- per-code squared norms + max norm --------------------------
__global__ void __launch_bounds__(256) k_prepw(const float* __restrict__ w) {
    int warp = (blockIdx.x * 256 + threadIdx.x) >> 5;
    int lane = threadIdx.x & 31;
    if (warp >= KCODES) return;
    const float4* p = (const float4*)(w + (size_t)warp * DIM);
    float s = 0.f;
#pragma unroll
    for (int j = 0; j < 2; j++) {
        float4 v = p[lane * 2 + j];
        s += v.x * v.x + v.y * v.y + v.z * v.z + v.w * v.w;
    }
#pragma unroll
    for (int o = 16; o; o >>= 1) s += __shfl_xor_sync(0xffffffffu, s, o);
    if (lane == 0) {
        g_w2[warp] = s;
        atomicMax(&g_wmax2_bits, __float_as_uint(s));
    }
}

// ---------------- transpose z_e [B,D,HW] -> flat [B*HW, D] --------------------
__global__ void k_transpose(const float* __restrict__ ze) {
    __shared__ float tile[32][33];
    int b  = blockIdx.z;
    int d0 = blockIdx.x * 32;
    int h0 = blockIdx.y * 32;
    int tx = threadIdx.x, ty = threadIdx.y;  // block (32, 8)
#pragma unroll
    for (int i = 0; i < 32; i += 8)
        tile[ty + i][tx] = ze[(size_t)(b * DIM + d0 + ty + i) * HWSZ + h0 + tx];
    __syncthreads();
#pragma unroll
    for (int i = 0; i < 32; i += 8)
        g_flat[(size_t)(b * HWSZ + h0 + ty + i) * DIM + d0 + tx] = tile[tx][ty + i];
}

// ---------------- argmax of (gumbel + 2 z.w - |w|^2) via bounded pruning ------
__global__ void __launch_bounds__(256) k_argmax(const float* __restrict__ gum,
                                                const float* __restrict__ w,
                                                float* __restrict__ out,
                                                int write_extras) {
    const int n = blockIdx.x;
    const int t = threadIdx.x;
    const int lane = t & 31, wrp = t >> 5;
    __shared__ float sh_z[DIM];
    __shared__ int   sh_cand[CAP];
    __shared__ int   sh_cnt;
    __shared__ float sh_red[8];
    __shared__ float sh_vs[256];
    __shared__ int   sh_ks[256];

    // load this token's z row (coalesced), compute |z|^2
    float zv = g_flat[n * DIM + t];
    sh_z[t] = zv;
    if (t == 0) sh_cnt = 0;
    float s = zv * zv;
#pragma unroll
    for (int o = 16; o; o >>= 1) s += __shfl_xor_sync(0xffffffffu, s, o);
    if (lane == 0) sh_red[wrp] = s;
    __syncthreads();
    float zn2 = 0.f;
#pragma unroll
    for (int i = 0; i < 8; i++) zn2 += sh_red[i];
    float wmax2 = __uint_as_float(g_wmax2_bits);
    // |logit_k| range bound: 2 z.w in [-2|z|wmax, 2|z|wmax]; -|w|^2 in [-wmax2, 0]
    float delta = 4.f * sqrtf(zn2) * sqrtf(wmax2) + wmax2 + 1e-5f;
    __syncthreads();

    // single pass over gumbel row; keep the 32 values per thread in registers
    const float4* row4 = (const float4*)(gum + (size_t)n * KCODES);
    float4 vv[8];
#pragma unroll
    for (int j = 0; j < 8; j++) vv[j] = row4[t + j * 256];
    float m = -INFINITY;
#pragma unroll
    for (int j = 0; j < 8; j++) {
        float4 v = vv[j];
        m = fmaxf(m, fmaxf(fmaxf(v.x, v.y), fmaxf(v.z, v.w)));
    }
#pragma unroll
    for (int o = 16; o; o >>= 1) m = fmaxf(m, __shfl_xor_sync(0xffffffffu, m, o));
    if (lane == 0) sh_red[wrp] = m;
    __syncthreads();
    float gmax = sh_red[0];
#pragma unroll
    for (int i = 1; i < 8; i++) gmax = fmaxf(gmax, sh_red[i]);

    // collect candidates from registers (no second gumbel read)
    float thresh = gmax - delta;
#pragma unroll
    for (int j = 0; j < 8; j++) {
        float4 v = vv[j];
        int kb = (t + j * 256) << 2;
        if (v.x >= thresh) { int p = atomicAdd(&sh_cnt, 1); if (p < CAP) sh_cand[p] = kb; }
        if (v.y >= thresh) { int p = atomicAdd(&sh_cnt, 1); if (p < CAP) sh_cand[p] = kb + 1; }
        if (v.z >= thresh) { int p = atomicAdd(&sh_cnt, 1); if (p < CAP) sh_cand[p] = kb + 2; }
        if (v.w >= thresh) { int p = atomicAdd(&sh_cnt, 1); if (p < CAP) sh_cand[p] = kb + 3; }
    }
    __syncthreads();
    int cnt = sh_cnt;
    int best_k = -1;

    if (cnt == 1) {
        best_k = sh_cand[0];                       // ~87% of tokens
    } else if (cnt <= CAP) {
        float best_s = -INFINITY;
        for (int c = 0; c < cnt; c++) {
            int k = sh_cand[c];
            float p = sh_z[t] * __ldg(&w[(size_t)k * DIM + t]);
#pragma unroll
            for (int o = 16; o; o >>= 1) p += __shfl_xor_sync(0xffffffffu, p, o);
            if (lane == 0) sh_red[wrp] = p;
            __syncthreads();
            if (t == 0) {
                float dot = 0.f;
#pragma unroll
                for (int i = 0; i < 8; i++) dot += sh_red[i];
                float sc = __ldg(&gum[(size_t)n * KCODES + k]) + 2.f * dot - g_w2[k];
                if (sc > best_s || (sc == best_s && k < best_k)) { best_s = sc; best_k = k; }
            }
            __syncthreads();
        }
    } else {
        // statistically unreachable fallback: exact full scan
        float bs = -INFINITY; int bk = KCODES;
        for (int k = t; k < KCODES; k += 256) {
            float dot = 0.f;
            for (int d = 0; d < DIM; d++) dot += sh_z[d] * w[(size_t)k * DIM + d];
            float sc = __ldg(&gum[(size_t)n * KCODES + k]) + 2.f * dot - g_w2[k];
            if (sc > bs || (sc == bs && k < bk)) { bs = sc; bk = k; }
        }
        sh_vs[t] = bs; sh_ks[t] = bk;
        __syncthreads();
        for (int off = 128; off; off >>= 1) {
            if (t < off) {
                float ov = sh_vs[t + off]; int ok = sh_ks[t + off];
                if (ov > sh_vs[t] || (ov == sh_vs[t] && ok < sh_ks[t])) { sh_vs[t] = ov; sh_ks[t] = ok; }
            }
            __syncthreads();
        }
        best_k = sh_ks[0];
    }

    if (t == 0) {
        g_idx[n] = best_k;
        atomicAdd(&g_hist[best_k], 1);
        if (write_extras) out[ZQ_ELEMS + 2 + n] = (float)best_k;
    }
}

// -------- gather z_q = weight[idx], STE write (NCHW), loss accumulation -------
__global__ void __launch_bounds__(256) k_gather(const float* __restrict__ ze,
                                                const float* __restrict__ w,
                                                float* __restrict__ out) {
    int i  = blockIdx.x * 256 + threadIdx.x;      // NCHW linear index
    int hw = i & (HWSZ - 1);
    int d  = (i >> 10) & (DIM - 1);
    int b  = i >> 18;
    int n  = (b << 10) | hw;
    int k  = g_idx[n];
    float zq  = __ldg(&w[(size_t)k * DIM + d]);   // scattered 4B, L2-resident (8MB)
    float zev = ze[i];                            // coalesced
    float df  = zq - zev;
    out[i] = zev + df;                            // mimic reference STE arithmetic exactly
    float s = df * df;
#pragma unroll
    for (int o = 16; o; o >>= 1) s += __shfl_xor_sync(0xffffffffu, s, o);
    __shared__ float sr[8];
    if ((threadIdx.x & 31) == 0) sr[threadIdx.x >> 5] = s;
    __syncthreads();
    if (threadIdx.x == 0) {
        float tot = 0.f;
#pragma unroll
        for (int q = 0; q < 8; q++) tot += sr[q];
        atomicAdd(&g_loss, (double)tot);
    }
}

// ---------------- scalars: vq_loss & perplexity -------------------------------
__global__ void __launch_bounds__(256) k_final(float* __restrict__ out, int write_extras) {
    if (!write_extras) return;
    int t = threadIdx.x;
    double acc = 0.0;
    for (int k = t; k < KCODES; k += 256) {
        float p = (float)g_hist[k] * (1.0f / (float)NTOK);
        acc += (double)(p * logf(p + 1e-10f));
    }
#pragma unroll
    for (int o = 16; o; o >>= 1) acc += __shfl_xor_sync(0xffffffffu, acc, o);
    __shared__ double sr[8];
    if ((t & 31) == 0) sr[t >> 5] = acc;
    __syncthreads();
    if (t == 0) {
        double tot = 0.0;
        for (int q = 0; q < 8; q++) tot += sr[q];
        out[ZQ_ELEMS]     = (float)(1.25 * g_loss / (double)ZQ_ELEMS);  // codebook + beta*commit
        out[ZQ_ELEMS + 1] = (float)exp(-tot);                           // perplexity
    }
}

extern "C" void kernel_launch(void* const* d_in, const int* in_sizes, int n_in,
                              void* d_out, int out_size) {
    // identify gumbel by its unique size; remaining two in metadata order: z_e, weight
    const float* gum = nullptr;
    const float* small[2] = {nullptr, nullptr};
    int ns = 0;
    for (int i = 0; i < n_in; i++) {
        if (in_sizes[i] == KCODES * NTOK) gum = (const float*)d_in[i];
        else if (ns < 2) small[ns++] = (const float*)d_in[i];
    }
    const float* z_e = small[0];
    const float* w   = small[1];
    float* out = (float*)d_out;
    int write_extras = (out_size >= OUT_FULL) ? 1 : 0;

    k_zero<<<(KCODES + 255) / 256, 256>>>();
    k_prepw<<<KCODES / 8, 256>>>(w);
    dim3 tg(DIM / 32, HWSZ / 32, 8);
    k_transpose<<<tg, dim3(32, 8)>>>(z_e);
    k_argmax<<<NTOK, 256>>>(gum, w, out, write_extras);
    k_gather<<<ZQ_ELEMS / 256, 256>>>(z_e, w, out);
    k_final<<<1, 256>>>(out, write_extras);
}

// round 2
// speedup vs baseline: 1.3058x; 1.3058x over previous
#include <cuda_runtime.h>
#include <math.h>

#define KCODES   8192
#define DIM      256
#define NTOK     8192       // B*H*W
#define HWSZ     1024
#define ZQ_ELEMS 2097152
#define OUT_FULL (ZQ_ELEMS + 2 + NTOK)
#define CAP      256

static __device__ float    g_flat[NTOK * DIM];
static __device__ float    g_w2[KCODES];
static __device__ unsigned g_wmax2_bits;       // monotone max, idempotent across replays
static __device__ int      g_idx[NTOK];
static __device__ int      g_hist[KCODES];
static __device__ double   g_loss;
static __device__ unsigned g_done;

// ============ Kernel A: transpose + per-code norms + zero scratch ============
__global__ void __launch_bounds__(256) k_prep(const float* __restrict__ ze,
                                              const float* __restrict__ w) {
    int blk = blockIdx.x, t = threadIdx.x;
    if (blk < 2048) {
        // transpose z_e [B,D,HW] -> g_flat [B*HW, D], 32x32 tiles
        __shared__ float tile[32][33];
        int b = blk >> 8, rem = blk & 255;
        int d0 = (rem >> 5) << 5;
        int h0 = (rem & 31) << 5;
        int tx = t & 31, ty = t >> 5;
#pragma unroll
        for (int i = 0; i < 32; i += 8)
            tile[ty + i][tx] = ze[(size_t)(b * DIM + d0 + ty + i) * HWSZ + h0 + tx];
        __syncthreads();
#pragma unroll
        for (int i = 0; i < 32; i += 8)
            g_flat[(size_t)(b * HWSZ + h0 + ty + i) * DIM + d0 + tx] = tile[tx][ty + i];
    } else if (blk < 3072) {
        // |w_k|^2 (one warp per row) + global max
        int warp = ((blk - 2048) << 8 | t) >> 5;
        int lane = t & 31;
        const float4* p = (const float4*)(w + (size_t)warp * DIM);
        float s = 0.f;
#pragma unroll
        for (int j = 0; j < 2; j++) {
            float4 v = p[lane * 2 + j];
            s += v.x * v.x + v.y * v.y + v.z * v.z + v.w * v.w;
        }
#pragma unroll
        for (int o = 16; o; o >>= 1) s += __shfl_xor_sync(0xffffffffu, s, o);
        if (lane == 0) {
            g_w2[warp] = s;
            atomicMax(&g_wmax2_bits, __float_as_uint(s));
        }
    } else {
        int i = ((blk - 3072) << 8) | t;
        g_hist[i] = 0;
        if (i == 0) { g_loss = 0.0; g_done = 0u; }
    }
}

// ============ Kernel B: argmax(gumbel + 2 z.w - |w|^2) via bounded pruning ====
__global__ void __launch_bounds__(256) k_argmax(const float* __restrict__ gum,
                                                const float* __restrict__ w,
                                                float* __restrict__ out,
                                                int write_extras) {
    const int n = blockIdx.x;
    const int t = threadIdx.x;
    const int lane = t & 31, wrp = t >> 5;
    __shared__ float sh_z[DIM];
    __shared__ int   sh_cand[CAP];
    __shared__ float sh_cg[CAP];
    __shared__ int   sh_cnt;
    __shared__ float sh_red[8];
    __shared__ float sh_bv[8];
    __shared__ int   sh_bk[8];

    // token's z row + |z|^2
    float zv = g_flat[n * DIM + t];
    sh_z[t] = zv;
    if (t == 0) sh_cnt = 0;
    float s = zv * zv;
#pragma unroll
    for (int o = 16; o; o >>= 1) s += __shfl_xor_sync(0xffffffffu, s, o);
    if (lane == 0) sh_red[wrp] = s;
    __syncthreads();
    float zn2 = 0.f;
#pragma unroll
    for (int i = 0; i < 8; i++) zn2 += sh_red[i];
    float wmax2 = __uint_as_float(g_wmax2_bits);
    float delta = 4.f * sqrtf(zn2) * sqrtf(wmax2) + wmax2 + 1e-5f;
    __syncthreads();

    // single streaming pass over the gumbel row; keep 32 values in registers
    const float4* row4 = (const float4*)(gum + (size_t)n * KCODES);
    float4 vv[8];
#pragma unroll
    for (int j = 0; j < 8; j++) vv[j] = __ldcs(row4 + t + j * 256);
    float m = -INFINITY;
#pragma unroll
    for (int j = 0; j < 8; j++) {
        float4 v = vv[j];
        m = fmaxf(m, fmaxf(fmaxf(v.x, v.y), fmaxf(v.z, v.w)));
    }
#pragma unroll
    for (int o = 16; o; o >>= 1) m = fmaxf(m, __shfl_xor_sync(0xffffffffu, m, o));
    if (lane == 0) sh_red[wrp] = m;
    __syncthreads();
    float gmax = sh_red[0];
#pragma unroll
    for (int i = 1; i < 8; i++) gmax = fmaxf(gmax, sh_red[i]);

    // collect candidates (index + gumbel value) from registers
    float thresh = gmax - delta;
#pragma unroll
    for (int j = 0; j < 8; j++) {
        float4 v = vv[j];
        int kb = (t + j * 256) << 2;
        if (v.x >= thresh) { int p = atomicAdd(&sh_cnt, 1); if (p < CAP) { sh_cand[p] = kb;     sh_cg[p] = v.x; } }
        if (v.y >= thresh) { int p = atomicAdd(&sh_cnt, 1); if (p < CAP) { sh_cand[p] = kb + 1; sh_cg[p] = v.y; } }
        if (v.z >= thresh) { int p = atomicAdd(&sh_cnt, 1); if (p < CAP) { sh_cand[p] = kb + 2; sh_cg[p] = v.z; } }
        if (v.w >= thresh) { int p = atomicAdd(&sh_cnt, 1); if (p < CAP) { sh_cand[p] = kb + 3; sh_cg[p] = v.w; } }
    }
    __syncthreads();
    int cnt = sh_cnt;
    int best_k = -1;

    if (cnt == 1) {
        best_k = sh_cand[0];                         // ~87% of tokens
    } else if (cnt <= CAP) {
        // warp-parallel candidate scoring: warp handles candidates wrp, wrp+8, ...
        float bv = -INFINITY; int bk = KCODES;
        for (int c = wrp; c < cnt; c += 8) {
            int k = sh_cand[c];
            const float4* wr = (const float4*)(w + (size_t)k * DIM);
            float dot = 0.f;
#pragma unroll
            for (int j = 0; j < 2; j++) {
                float4 a = __ldg(wr + lane * 2 + j);
                int db = lane * 8 + j * 4;
                dot += a.x * sh_z[db] + a.y * sh_z[db + 1] + a.z * sh_z[db + 2] + a.w * sh_z[db + 3];
            }
#pragma unroll
            for (int o = 16; o; o >>= 1) dot += __shfl_xor_sync(0xffffffffu, dot, o);
            float sc = sh_cg[c] + 2.f * dot - g_w2[k];
            if (sc > bv || (sc == bv && k < bk)) { bv = sc; bk = k; }
        }
        if (lane == 0) { sh_bv[wrp] = bv; sh_bk[wrp] = bk; }
        __syncthreads();
        if (t == 0) {
            float fb = -INFINITY; int fk = KCODES;
#pragma unroll
            for (int i = 0; i < 8; i++) {
                float v = sh_bv[i]; int k = sh_bk[i];
                if (v > fb || (v == fb && k < fk)) { fb = v; fk = k; }
            }
            best_k = fk;
        }
    } else {
        // statistically unreachable safety net: exact full scan
        float bs = -INFINITY; int bk = KCODES;
        for (int k = t; k < KCODES; k += 256) {
            float dot = 0.f;
            for (int d = 0; d < DIM; d++) dot += sh_z[d] * w[(size_t)k * DIM + d];
            float sc = __ldg(&gum[(size_t)n * KCODES + k]) + 2.f * dot - g_w2[k];
            if (sc > bs || (sc == bs && k < bk)) { bs = sc; bk = k; }
        }
        __syncthreads();
        sh_cg[t] = bs; sh_cand[t] = bk;
        __syncthreads();
        for (int off = 128; off; off >>= 1) {
            if (t < off) {
                float ov = sh_cg[t + off]; int ok = sh_cand[t + off];
                if (ov > sh_cg[t] || (ov == sh_cg[t] && ok < sh_cand[t])) { sh_cg[t] = ov; sh_cand[t] = ok; }
            }
            __syncthreads();
        }
        best_k = sh_cand[0];
    }

    if (t == 0) {
        g_idx[n] = best_k;
        atomicAdd(&g_hist[best_k], 1);
        if (write_extras) out[ZQ_ELEMS + 2 + n] = (float)best_k;
    }
}

// ==== Kernel C: coalesced gather + STE write + loss + (last block) scalars ====
__global__ void __launch_bounds__(256) k_out(const float* __restrict__ ze,
                                             const float* __restrict__ w,
                                             float* __restrict__ out,
                                             int write_extras) {
    __shared__ float tile[32][33];
    __shared__ int   kk[32];
    __shared__ float sr[8];
    __shared__ int   s_last;
    int blk = blockIdx.x, t = threadIdx.x;
    int tx = t & 31, ty = t >> 5;
    int b = blk >> 8, rem = blk & 255;
    int d0 = (rem >> 5) << 5;
    int hw0 = (rem & 31) << 5;

    if (t < 32) kk[t] = g_idx[b * HWSZ + hw0 + t];
    __syncthreads();
    // coalesced load of 32 codebook rows (32 dims each) into smem tile[token][d]
#pragma unroll
    for (int i = 0; i < 4; i++) {
        int tok = ty + i * 8;
        tile[tok][tx] = __ldg(&w[(size_t)kk[tok] * DIM + d0 + tx]);
    }
    __syncthreads();

    float acc = 0.f;
#pragma unroll
    for (int i = 0; i < 4; i++) {
        int dd = ty + i * 8;
        size_t gi = (size_t)(b * DIM + d0 + dd) * HWSZ + hw0 + tx;  // NCHW, coalesced
        float zq  = tile[tx][dd];
        float zev = ze[gi];
        float df  = zq - zev;
        out[gi]   = zev + df;     // mirror reference STE arithmetic
        acc += df * df;
    }
#pragma unroll
    for (int o = 16; o; o >>= 1) acc += __shfl_xor_sync(0xffffffffu, acc, o);
    if ((t & 31) == 0) sr[t >> 5] = acc;
    __syncthreads();
    if (t == 0) {
        float tot = 0.f;
#pragma unroll
        for (int q = 0; q < 8; q++) tot += sr[q];
        atomicAdd(&g_loss, (double)tot);
        __threadfence();
        unsigned old = atomicAdd(&g_done, 1u);
        s_last = (old == gridDim.x - 1) ? 1 : 0;
    }
    __syncthreads();

    if (s_last && write_extras) {
        // final scalars computed by the last block to finish
        double accp = 0.0;
        for (int k = t; k < KCODES; k += 256) {
            float p = (float)g_hist[k] * (1.0f / (float)NTOK);
            accp += (double)(p * logf(p + 1e-10f));
        }
#pragma unroll
        for (int o = 16; o; o >>= 1) accp += __shfl_xor_sync(0xffffffffu, accp, o);
        __shared__ double dr[8];
        if ((t & 31) == 0) dr[t >> 5] = accp;
        __syncthreads();
        if (t == 0) {
            double tot = 0.0;
#pragma unroll
            for (int q = 0; q < 8; q++) tot += dr[q];
            double loss = *((volatile double*)&g_loss);
            out[ZQ_ELEMS]     = (float)(1.25 * loss / (double)ZQ_ELEMS);
            out[ZQ_ELEMS + 1] = (float)exp(-tot);
        }
    }
}

extern "C" void kernel_launch(void* const* d_in, const int* in_sizes, int n_in,
                              void* d_out, int out_size) {
    const float* gum = nullptr;
    const float* small[2] = {nullptr, nullptr};
    int ns = 0;
    for (int i = 0; i < n_in; i++) {
        if (in_sizes[i] == KCODES * NTOK) gum = (const float*)d_in[i];
        else if (ns < 2) small[ns++] = (const float*)d_in[i];
    }
    const float* z_e = small[0];
    const float* w   = small[1];
    float* out = (float*)d_out;
    int write_extras = (out_size >= OUT_FULL) ? 1 : 0;

    k_prep<<<3104, 256>>>(z_e, w);
    k_argmax<<<NTOK, 256>>>(gum, w, out, write_extras);
    k_out<<<2048, 256>>>(z_e, w, out, write_extras);
}